// round 2
// baseline (speedup 1.0000x reference)
#include <cuda_runtime.h>
#include <math.h>

#define NN 100000
#define NE 1600000
#define NB 1024
#define HID 128

// ---------------- device scratch (static allocations are allowed) -------------
__device__ int   g_cnt[NN];
__device__ float g_dinv[NN];
__device__ int   g_rowptr[NN + 1];
__device__ int   g_cursor[NN];
__device__ int   g_bsums[256];
__device__ int   g_csr_src[NE];
__device__ float g_csr_norm[NE];
__device__ float g_H[(size_t)NN * HID];
__device__ float g_X[(size_t)NN * HID];
__device__ int   g_gstart[NB];
__device__ int   g_gcnt[NB];
__device__ float g_cat[NB * 384];
__device__ float g_t1[NB * 256];
__device__ float g_f1[NB * 256];
__device__ float g_f2[NB * 128];

// ---------------- setup kernels ----------------------------------------------
__global__ void k_init(int n, int b) {
    int i = blockIdx.x * blockDim.x + threadIdx.x;
    int stride = gridDim.x * blockDim.x;
    for (int j = i; j < n; j += stride) g_cnt[j] = 0;
    for (int j = i; j < b; j += stride) { g_gstart[j] = 0x7fffffff; g_gcnt[j] = 0; }
}

__global__ void k_count(const int* __restrict__ dst, int E) {
    int e = blockIdx.x * blockDim.x + threadIdx.x;
    if (e < E) atomicAdd(&g_cnt[dst[e]], 1);
}

__global__ void k_graph_ranges(const int* __restrict__ batch, int n) {
    int i = blockIdx.x * blockDim.x + threadIdx.x;
    if (i < n) {
        int g = batch[i];
        atomicAdd(&g_gcnt[g], 1);
        atomicMin(&g_gstart[g], i);
    }
}

__global__ void k_dinv(int n) {
    int i = blockIdx.x * blockDim.x + threadIdx.x;
    if (i < n) g_dinv[i] = rsqrtf((float)(g_cnt[i] + 2));
}

// block-wise exclusive scan (1024/block) of g_cnt into g_rowptr, block sums out
__global__ void k_scan1(int n) {
    __shared__ int s[1024];
    int i = blockIdx.x * 1024 + threadIdx.x;
    int v = (i < n) ? g_cnt[i] : 0;
    s[threadIdx.x] = v;
    __syncthreads();
    for (int off = 1; off < 1024; off <<= 1) {
        int t = (threadIdx.x >= off) ? s[threadIdx.x - off] : 0;
        __syncthreads();
        s[threadIdx.x] += t;
        __syncthreads();
    }
    if (i < n) g_rowptr[i] = s[threadIdx.x] - v;   // exclusive within block
    if (threadIdx.x == 1023) g_bsums[blockIdx.x] = s[1023];
}

__global__ void k_scan2(int nb) {
    if (threadIdx.x == 0 && blockIdx.x == 0) {
        int acc = 0;
        for (int i = 0; i < nb; i++) { int v = g_bsums[i]; g_bsums[i] = acc; acc += v; }
    }
}

__global__ void k_scan3(int n, int E) {
    int i = blockIdx.x * 1024 + threadIdx.x;
    if (i < n) {
        int v = g_rowptr[i] + g_bsums[blockIdx.x];
        g_rowptr[i] = v;
        g_cursor[i] = v;
    }
    if (i == 0) g_rowptr[n] = E;
}

__global__ void k_scatter(const int* __restrict__ src, const int* __restrict__ dst, int E) {
    int e = blockIdx.x * blockDim.x + threadIdx.x;
    if (e < E) {
        int s = src[e], d = dst[e];
        int p = atomicAdd(&g_cursor[d], 1);
        g_csr_src[p] = s;
        g_csr_norm[p] = g_dinv[s] * g_dinv[d];
    }
}

// ---------------- main GEMM: H[n x 128] = A[n x K] @ W[K x 128] ---------------
#define BM 128
#define BK 16
__global__ __launch_bounds__(256) void k_gemm128(const float* __restrict__ A,
                                                 const float* __restrict__ W,
                                                 int M, int K) {
    __shared__ float As[BK][BM];
    __shared__ float Bs[BK][128];
    int block_m = blockIdx.x * BM;
    int tid = threadIdx.x;
    int tx = tid & 15, ty = tid >> 4;   // 16 x 16
    float acc[8][8];
#pragma unroll
    for (int i = 0; i < 8; i++)
#pragma unroll
        for (int j = 0; j < 8; j++) acc[i][j] = 0.f;

    for (int k0 = 0; k0 < K; k0 += BK) {
        // A tile: 128 x 16 = 512 float4, 2 per thread; store transposed
#pragma unroll
        for (int r = 0; r < 2; r++) {
            int idx = tid + r * 256;
            int m = idx >> 2;            // 4 float4 per row of 16
            int kk = (idx & 3) << 2;
            float4 v = make_float4(0.f, 0.f, 0.f, 0.f);
            int gm = block_m + m;
            if (gm < M) v = *(const float4*)(A + (size_t)gm * K + k0 + kk);
            As[kk + 0][m] = v.x; As[kk + 1][m] = v.y;
            As[kk + 2][m] = v.z; As[kk + 3][m] = v.w;
        }
        // W tile: 16 x 128 = 512 float4
#pragma unroll
        for (int r = 0; r < 2; r++) {
            int idx = tid + r * 256;
            int kk = idx >> 5;           // 32 float4 per row of 128
            int nn = (idx & 31) << 2;
            *(float4*)&Bs[kk][nn] = *(const float4*)(W + (size_t)(k0 + kk) * 128 + nn);
        }
        __syncthreads();
#pragma unroll
        for (int k = 0; k < BK; k++) {
            float a[8], b[8];
            *(float4*)&a[0] = *(const float4*)&As[k][ty * 8];
            *(float4*)&a[4] = *(const float4*)&As[k][ty * 8 + 4];
            *(float4*)&b[0] = *(const float4*)&Bs[k][tx * 8];
            *(float4*)&b[4] = *(const float4*)&Bs[k][tx * 8 + 4];
#pragma unroll
            for (int i = 0; i < 8; i++)
#pragma unroll
                for (int j = 0; j < 8; j++) acc[i][j] += a[i] * b[j];
        }
        __syncthreads();
    }
#pragma unroll
    for (int i = 0; i < 8; i++) {
        int gm = block_m + ty * 8 + i;
        if (gm < M) {
            *(float4*)(g_H + (size_t)gm * 128 + tx * 8)     = *(float4*)&acc[i][0];
            *(float4*)(g_H + (size_t)gm * 128 + tx * 8 + 4) = *(float4*)&acc[i][4];
        }
    }
}

// ---------------- edge aggregation: one warp per node, atomic-free ------------
__global__ void k_aggregate(const float* __restrict__ bias, int n) {
    int warp = (blockIdx.x * blockDim.x + threadIdx.x) >> 5;
    int lane = threadIdx.x & 31;
    if (warp >= n) return;
    float di = g_dinv[warp];
    float sw = 2.f * di * di;                                   // two self-loops
    float4 v = *(const float4*)(g_H + (size_t)warp * 128 + lane * 4);
    float4 acc = make_float4(v.x * sw, v.y * sw, v.z * sw, v.w * sw);
    int beg = g_rowptr[warp], end = g_rowptr[warp + 1];
    for (int e = beg; e < end; e++) {
        int s = g_csr_src[e];
        float w = g_csr_norm[e];
        float4 hv = *(const float4*)(g_H + (size_t)s * 128 + lane * 4);
        acc.x += w * hv.x; acc.y += w * hv.y;
        acc.z += w * hv.z; acc.w += w * hv.w;
    }
    float4 bb = *(const float4*)(bias + lane * 4);
    acc.x = fmaxf(acc.x + bb.x, 0.f);
    acc.y = fmaxf(acc.y + bb.y, 0.f);
    acc.z = fmaxf(acc.z + bb.z, 0.f);
    acc.w = fmaxf(acc.w + bb.w, 0.f);
    *(float4*)(g_X + (size_t)warp * 128 + lane * 4) = acc;
}

// ---------------- pooling: mean + max per (sorted) graph range ----------------
__global__ void k_pool(int n) {
    int g = blockIdx.x;
    int d = threadIdx.x;          // 128
    int beg = g_gstart[g], cnt = g_gcnt[g];
    float s = 0.f, mx = -3.402823e38f;
    for (int i = 0; i < cnt; i++) {
        float v = g_X[(size_t)(beg + i) * 128 + d];
        s += v;
        mx = fmaxf(mx, v);
    }
    float mean = (cnt > 0) ? s / (float)cnt : 0.f;
    if (cnt == 0) mx = 0.f;
    g_cat[(size_t)g * 384 + d]       = mean;
    g_cat[(size_t)g * 384 + 128 + d] = mx;
}

// ---------------- small dense layers (one block per row) ----------------------
// act: 1 = relu, 2 = sigmoid
__global__ void k_dense(const float* __restrict__ A, int lda,
                        const float* __restrict__ W, const float* __restrict__ b,
                        float* __restrict__ C, int ldc, int K, int N, int act) {
    __shared__ float sA[384];
    int m = blockIdx.x;
    for (int k = threadIdx.x; k < K; k += blockDim.x) sA[k] = A[(size_t)m * lda + k];
    __syncthreads();
    for (int nidx = threadIdx.x; nidx < N; nidx += blockDim.x) {
        float acc = b[nidx];
        for (int k = 0; k < K; k++) acc += sA[k] * W[(size_t)k * N + nidx];
        if (act == 1) acc = fmaxf(acc, 0.f);
        else if (act == 2) acc = 1.f / (1.f + expf(-acc));
        C[(size_t)m * ldc + nidx] = acc;
    }
}

// ---------------- launch ------------------------------------------------------
extern "C" void kernel_launch(void* const* d_in, const int* in_sizes, int n_in,
                              void* d_out, int out_size) {
    const float* x_graph = (const float*)d_in[0];
    const int*   edge    = (const int*)d_in[1];
    const int*   batch   = (const int*)d_in[2];
    const float* x_tab   = (const float*)d_in[3];
    const float* Wg1 = (const float*)d_in[4];  const float* bg1 = (const float*)d_in[5];
    const float* Wg2 = (const float*)d_in[6];  const float* bg2 = (const float*)d_in[7];
    const float* Wg3 = (const float*)d_in[8];  const float* bg3 = (const float*)d_in[9];
    const float* Wg4 = (const float*)d_in[10]; const float* bg4 = (const float*)d_in[11];
    const float* Wt1 = (const float*)d_in[12]; const float* bt1 = (const float*)d_in[13];
    const float* Wt2 = (const float*)d_in[14]; const float* bt2 = (const float*)d_in[15];
    const float* Wf1 = (const float*)d_in[16]; const float* bf1 = (const float*)d_in[17];
    const float* Wf2 = (const float*)d_in[18]; const float* bf2 = (const float*)d_in[19];
    const float* Wf3 = (const float*)d_in[20]; const float* bf3 = (const float*)d_in[21];

    int n = in_sizes[0] / 64;     // 100000
    int E = in_sizes[1] / 2;      // 1600000
    int B = in_sizes[3] / 200;    // 1024
    const int* src = edge;
    const int* dst = edge + E;

    float *Xp, *catp, *t1p, *f1p, *f2p;
    cudaGetSymbolAddress((void**)&Xp,  g_X);
    cudaGetSymbolAddress((void**)&catp, g_cat);
    cudaGetSymbolAddress((void**)&t1p, g_t1);
    cudaGetSymbolAddress((void**)&f1p, g_f1);
    cudaGetSymbolAddress((void**)&f2p, g_f2);

    int nb = (n + 1023) / 1024;

    k_init<<<256, 256>>>(n, B);
    k_count<<<(E + 255) / 256, 256>>>(dst, E);
    k_graph_ranges<<<(n + 255) / 256, 256>>>(batch, n);
    k_dinv<<<(n + 255) / 256, 256>>>(n);
    k_scan1<<<nb, 1024>>>(n);
    k_scan2<<<1, 32>>>(nb);
    k_scan3<<<nb, 1024>>>(n, E);
    k_scatter<<<(E + 255) / 256, 256>>>(src, dst, E);

    int gemm_blocks = (n + BM - 1) / BM;
    int agg_blocks  = (n * 32 + 255) / 256;

    // layer 1 (K = 64)
    k_gemm128<<<gemm_blocks, 256>>>(x_graph, Wg1, n, 64);
    k_aggregate<<<agg_blocks, 256>>>(bg1, n);
    // layer 2
    k_gemm128<<<gemm_blocks, 256>>>(Xp, Wg2, n, 128);
    k_aggregate<<<agg_blocks, 256>>>(bg2, n);
    // layer 3
    k_gemm128<<<gemm_blocks, 256>>>(Xp, Wg3, n, 128);
    k_aggregate<<<agg_blocks, 256>>>(bg3, n);
    // layer 4
    k_gemm128<<<gemm_blocks, 256>>>(Xp, Wg4, n, 128);
    k_aggregate<<<agg_blocks, 256>>>(bg4, n);

    // pooling -> g_cat[:, 0:256]
    k_pool<<<B, 128>>>(n);

    // tabular branch -> g_cat[:, 256:384]
    k_dense<<<B, 256>>>(x_tab, 200, Wt1, bt1, t1p, 256, 200, 256, 1);
    k_dense<<<B, 256>>>(t1p, 256, Wt2, bt2, catp + 256, 384, 256, 128, 1);

    // fused head
    k_dense<<<B, 256>>>(catp, 384, Wf1, bf1, f1p, 256, 384, 256, 1);
    k_dense<<<B, 256>>>(f1p, 256, Wf2, bf2, f2p, 128, 256, 128, 1);
    k_dense<<<B, 32>>>(f2p, 128, Wf3, bf3, (float*)d_out, 1, 128, 1, 2);
}

// round 6
// speedup vs baseline: 1.1959x; 1.1959x over previous
#include <cuda_runtime.h>
#include <cuda_bf16.h>
#include <math.h>
#include <stdint.h>

#define NN 100000
#define NE 1600000
#define NB 1024
#define HID 128

// ---------------- device scratch ---------------------------------------------
__device__ int   g_cnt[NN];
__device__ float g_dinv[NN];
__device__ int   g_rowptr[NN + 1];
__device__ int   g_cursor[NN];
__device__ int   g_bsums[256];
__device__ int   g_csr_src[NE];
__device__ float g_csr_norm[NE];
__device__ float g_H[(size_t)NN * HID];
__device__ float g_X[(size_t)NN * HID];
__device__ int   g_gstart[NB];
__device__ int   g_gcnt[NB];
__device__ float g_cat[NB * 384];
__device__ float g_t1[NB * 256];
__device__ float g_f1[NB * 256];
__device__ float g_f2[NB * 128];
// bf16 hi/lo images of W^T per layer: row-major [128 n][K k]
__device__ __align__(16) unsigned char g_Wh[4][32768];
__device__ __align__(16) unsigned char g_Wl[4][32768];

// ---------------- ptx helpers -------------------------------------------------
__device__ __forceinline__ uint32_t smem_u32(const void* p) {
    uint32_t a;
    asm("{ .reg .u64 t; cvta.to.shared.u64 t, %1; cvt.u32.u64 %0, t; }" : "=r"(a) : "l"(p));
    return a;
}
__device__ __forceinline__ void ldm4(uint32_t* r, uint32_t addr) {
    asm volatile("ldmatrix.sync.aligned.m8n8.x4.shared.b16 {%0,%1,%2,%3}, [%4];"
                 : "=r"(r[0]), "=r"(r[1]), "=r"(r[2]), "=r"(r[3]) : "r"(addr));
}
__device__ __forceinline__ void mma_bf16(float* c, const uint32_t* a, uint32_t b0, uint32_t b1) {
    asm volatile("mma.sync.aligned.m16n8k16.row.col.f32.bf16.bf16.f32 "
                 "{%0,%1,%2,%3}, {%4,%5,%6,%7}, {%8,%9}, {%0,%1,%2,%3};"
                 : "+f"(c[0]), "+f"(c[1]), "+f"(c[2]), "+f"(c[3])
                 : "r"(a[0]), "r"(a[1]), "r"(a[2]), "r"(a[3]), "r"(b0), "r"(b1));
}

// ---------------- setup kernels ----------------------------------------------
__global__ void k_init(int n, int b) {
    int i = blockIdx.x * blockDim.x + threadIdx.x;
    int stride = gridDim.x * blockDim.x;
    for (int j = i; j < n; j += stride) g_cnt[j] = 0;
    for (int j = i; j < b; j += stride) { g_gstart[j] = 0x7fffffff; g_gcnt[j] = 0; }
}
__global__ void k_count(const int* __restrict__ dst, int E) {
    int e = blockIdx.x * blockDim.x + threadIdx.x;
    if (e < E) atomicAdd(&g_cnt[dst[e]], 1);
}
__global__ void k_graph_ranges(const int* __restrict__ batch, int n) {
    int i = blockIdx.x * blockDim.x + threadIdx.x;
    if (i < n) {
        int g = batch[i];
        atomicAdd(&g_gcnt[g], 1);
        atomicMin(&g_gstart[g], i);
    }
}
__global__ void k_dinv(int n) {
    int i = blockIdx.x * blockDim.x + threadIdx.x;
    if (i < n) g_dinv[i] = rsqrtf((float)(g_cnt[i] + 2));
}
__global__ void k_scan1(int n) {
    __shared__ int s[1024];
    int i = blockIdx.x * 1024 + threadIdx.x;
    int v = (i < n) ? g_cnt[i] : 0;
    s[threadIdx.x] = v;
    __syncthreads();
    for (int off = 1; off < 1024; off <<= 1) {
        int t = (threadIdx.x >= off) ? s[threadIdx.x - off] : 0;
        __syncthreads();
        s[threadIdx.x] += t;
        __syncthreads();
    }
    if (i < n) g_rowptr[i] = s[threadIdx.x] - v;
    if (threadIdx.x == 1023) g_bsums[blockIdx.x] = s[1023];
}
__global__ void k_scan2(int nb) {
    if (threadIdx.x == 0 && blockIdx.x == 0) {
        int acc = 0;
        for (int i = 0; i < nb; i++) { int v = g_bsums[i]; g_bsums[i] = acc; acc += v; }
    }
}
__global__ void k_scan3(int n, int E) {
    int i = blockIdx.x * 1024 + threadIdx.x;
    if (i < n) {
        int v = g_rowptr[i] + g_bsums[blockIdx.x];
        g_rowptr[i] = v;
        g_cursor[i] = v;
    }
    if (i == 0) g_rowptr[n] = E;
}
__global__ void k_scatter(const int* __restrict__ src, const int* __restrict__ dst, int E) {
    int e = blockIdx.x * blockDim.x + threadIdx.x;
    if (e < E) {
        int s = src[e], d = dst[e];
        int p = atomicAdd(&g_cursor[d], 1);
        g_csr_src[p] = s;
        g_csr_norm[p] = g_dinv[s] * g_dinv[d];
    }
}

// W [K x 128] fp32 -> W^T hi/lo bf16, row-major [n=128][K]
__global__ void k_prep_w(const float* __restrict__ W, int K, int layer) {
    int idx = blockIdx.x * blockDim.x + threadIdx.x;
    if (idx >= 128 * K) return;
    int nrow = idx / K, kcol = idx % K;
    float w = W[(size_t)kcol * 128 + nrow];
    __nv_bfloat16 hi = __float2bfloat16(w);
    __nv_bfloat16 lo = __float2bfloat16(w - __bfloat162float(hi));
    ((__nv_bfloat16*)g_Wh[layer])[idx] = hi;
    ((__nv_bfloat16*)g_Wl[layer])[idx] = lo;
}

// ---------------- mma.sync GEMM: H[M x 128] = A[M x K] @ W[K x 128] ----------
// hi/lo split: D = Ah*Wh + Al*Wh + Ah*Wl, fp32 accumulators.
// Block 128x128, 8 warps (4m x 2n), warp tile 32x64.
__global__ __launch_bounds__(256) void k_gemm_mma(const float* __restrict__ A,
                                                  const unsigned char* __restrict__ Wh,
                                                  const unsigned char* __restrict__ Wl,
                                                  float* __restrict__ Hout,
                                                  int M, int K) {
    extern __shared__ __align__(16) char smem[];
    const int SK = K + 8;                       // padded stride in halfs
    const size_t tile = (size_t)128 * SK;       // halfs per image
    __nv_bfloat16* sAh = (__nv_bfloat16*)smem;
    __nv_bfloat16* sAl = sAh + tile;
    __nv_bfloat16* sWh = sAl + tile;
    __nv_bfloat16* sWl = sWh + tile;

    const int tid = threadIdx.x;
    const int wid = tid >> 5, lane = tid & 31;
    const int wm = wid >> 1, wn = wid & 1;
    const int block_m = blockIdx.x * 128;

    // W images -> padded smem (8 halfs per thread-iter)
    {
        int k8 = K >> 3;
        for (int j = tid; j < 128 * k8; j += 256) {
            int r = j / k8, c = (j - r * k8) << 3;
            *(uint4*)(sWh + r * SK + c) = *(const uint4*)(Wh + ((size_t)r * K + c) * 2);
            *(uint4*)(sWl + r * SK + c) = *(const uint4*)(Wl + ((size_t)r * K + c) * 2);
        }
    }
    // A: fp32 -> hi/lo bf16, padded smem
    {
        int K4 = K >> 2;
        for (int j = tid; j < 32 * K; j += 256) {       // 128*K/4 float4s
            int r = j / K4, c = (j - r * K4) << 2;
            int gr = block_m + r; if (gr >= M) gr = M - 1;
            float4 v = *(const float4*)(A + (size_t)gr * K + c);
            __nv_bfloat162 h01 = __floats2bfloat162_rn(v.x, v.y);
            __nv_bfloat162 h23 = __floats2bfloat162_rn(v.z, v.w);
            float l0 = v.x - __low2float(h01), l1 = v.y - __high2float(h01);
            float l2 = v.z - __low2float(h23), l3 = v.w - __high2float(h23);
            __nv_bfloat162 lo01 = __floats2bfloat162_rn(l0, l1);
            __nv_bfloat162 lo23 = __floats2bfloat162_rn(l2, l3);
            *(uint2*)(sAh + r * SK + c) = make_uint2(*(uint32_t*)&h01, *(uint32_t*)&h23);
            *(uint2*)(sAl + r * SK + c) = make_uint2(*(uint32_t*)&lo01, *(uint32_t*)&lo23);
        }
    }
    __syncthreads();

    float acc[2][8][4];
#pragma unroll
    for (int i = 0; i < 2; i++)
#pragma unroll
        for (int j = 0; j < 8; j++)
#pragma unroll
            for (int q = 0; q < 4; q++) acc[i][j][q] = 0.f;

    const uint32_t uAh = smem_u32(sAh), uAl = smem_u32(sAl);
    const uint32_t uWh = smem_u32(sWh), uWl = smem_u32(sWl);
    // A ldmatrix lane address parts: row = wm*32 + mt*16 + (lane&15), koff = (lane>>4)*8
    const uint32_t a_row  = (uint32_t)(wm * 32 + (lane & 15));
    const uint32_t a_koff = (uint32_t)((lane >> 4) << 3);
    // B ldmatrix (x4, two n-tiles): row-in-16 = ((lane>>4)&1)*8 + (lane&7), koff = ((lane>>3)&1)*8
    const uint32_t b_row  = (uint32_t)(wn * 64 + (((lane >> 4) & 1) << 3) + (lane & 7));
    const uint32_t b_koff = (uint32_t)(((lane >> 3) & 1) << 3);

    const int nks = K >> 4;
    for (int ks = 0; ks < nks; ks++) {
        const uint32_t kb = (uint32_t)(ks << 4);
        uint32_t ah0[4], ah1[4], al0[4], al1[4];
        ldm4(ah0, uAh + ((a_row) * SK + kb + a_koff) * 2);
        ldm4(ah1, uAh + ((a_row + 16) * SK + kb + a_koff) * 2);
        ldm4(al0, uAl + ((a_row) * SK + kb + a_koff) * 2);
        ldm4(al1, uAl + ((a_row + 16) * SK + kb + a_koff) * 2);
#pragma unroll
        for (int np = 0; np < 4; np++) {
            uint32_t wh[4], wl[4];
            uint32_t boff = ((b_row + (uint32_t)(np << 4)) * SK + kb + b_koff) * 2;
            ldm4(wh, uWh + boff);
            ldm4(wl, uWl + boff);
            int n0 = np * 2, n1 = np * 2 + 1;
            // term Ah*Wh
            mma_bf16(acc[0][n0], ah0, wh[0], wh[1]);
            mma_bf16(acc[0][n1], ah0, wh[2], wh[3]);
            mma_bf16(acc[1][n0], ah1, wh[0], wh[1]);
            mma_bf16(acc[1][n1], ah1, wh[2], wh[3]);
            // term Al*Wh
            mma_bf16(acc[0][n0], al0, wh[0], wh[1]);
            mma_bf16(acc[0][n1], al0, wh[2], wh[3]);
            mma_bf16(acc[1][n0], al1, wh[0], wh[1]);
            mma_bf16(acc[1][n1], al1, wh[2], wh[3]);
            // term Ah*Wl
            mma_bf16(acc[0][n0], ah0, wl[0], wl[1]);
            mma_bf16(acc[0][n1], ah0, wl[2], wl[3]);
            mma_bf16(acc[1][n0], ah1, wl[0], wl[1]);
            mma_bf16(acc[1][n1], ah1, wl[2], wl[3]);
        }
    }

    // epilogue: c0,c1 -> row, c2,c3 -> row+8; cols 2*(lane&3)+{0,1}
    const int r_base = block_m + wm * 32 + (lane >> 2);
    const int c_base = wn * 64 + ((lane & 3) << 1);
#pragma unroll
    for (int mt = 0; mt < 2; mt++) {
        int r0 = r_base + mt * 16;
#pragma unroll
        for (int nt = 0; nt < 8; nt++) {
            int cc = c_base + nt * 8;
            if (r0 < M)
                *(float2*)(Hout + (size_t)r0 * 128 + cc) = make_float2(acc[mt][nt][0], acc[mt][nt][1]);
            if (r0 + 8 < M)
                *(float2*)(Hout + (size_t)(r0 + 8) * 128 + cc) = make_float2(acc[mt][nt][2], acc[mt][nt][3]);
        }
    }
}

// ---------------- edge aggregation: one warp per node, atomic-free ------------
__global__ void k_aggregate(const float* __restrict__ bias, int n) {
    int warp = (blockIdx.x * blockDim.x + threadIdx.x) >> 5;
    int lane = threadIdx.x & 31;
    if (warp >= n) return;
    float di = g_dinv[warp];
    float sw = 2.f * di * di;
    float4 v = *(const float4*)(g_H + (size_t)warp * 128 + lane * 4);
    float4 acc = make_float4(v.x * sw, v.y * sw, v.z * sw, v.w * sw);
    int beg = g_rowptr[warp], end = g_rowptr[warp + 1];
    for (int e = beg; e < end; e++) {
        int s = g_csr_src[e];
        float w = g_csr_norm[e];
        float4 hv = *(const float4*)(g_H + (size_t)s * 128 + lane * 4);
        acc.x += w * hv.x; acc.y += w * hv.y;
        acc.z += w * hv.z; acc.w += w * hv.w;
    }
    float4 bb = *(const float4*)(bias + lane * 4);
    acc.x = fmaxf(acc.x + bb.x, 0.f);
    acc.y = fmaxf(acc.y + bb.y, 0.f);
    acc.z = fmaxf(acc.z + bb.z, 0.f);
    acc.w = fmaxf(acc.w + bb.w, 0.f);
    *(float4*)(g_X + (size_t)warp * 128 + lane * 4) = acc;
}

// ---------------- pooling -----------------------------------------------------
__global__ void k_pool(int n) {
    int g = blockIdx.x;
    int d = threadIdx.x;
    int beg = g_gstart[g], cnt = g_gcnt[g];
    float s = 0.f, mx = -3.402823e38f;
    for (int i = 0; i < cnt; i++) {
        float v = g_X[(size_t)(beg + i) * 128 + d];
        s += v;
        mx = fmaxf(mx, v);
    }
    float mean = (cnt > 0) ? s / (float)cnt : 0.f;
    if (cnt == 0) mx = 0.f;
    g_cat[(size_t)g * 384 + d]       = mean;
    g_cat[(size_t)g * 384 + 128 + d] = mx;
}

// ---------------- small dense layers ------------------------------------------
__global__ void k_dense(const float* __restrict__ A, int lda,
                        const float* __restrict__ W, const float* __restrict__ b,
                        float* __restrict__ C, int ldc, int K, int N, int act) {
    __shared__ float sA[384];
    int m = blockIdx.x;
    for (int k = threadIdx.x; k < K; k += blockDim.x) sA[k] = A[(size_t)m * lda + k];
    __syncthreads();
    for (int nidx = threadIdx.x; nidx < N; nidx += blockDim.x) {
        float acc = b[nidx];
        for (int k = 0; k < K; k++) acc += sA[k] * W[(size_t)k * N + nidx];
        if (act == 1) acc = fmaxf(acc, 0.f);
        else if (act == 2) acc = 1.f / (1.f + expf(-acc));
        C[(size_t)m * ldc + nidx] = acc;
    }
}

// ---------------- launch ------------------------------------------------------
extern "C" void kernel_launch(void* const* d_in, const int* in_sizes, int n_in,
                              void* d_out, int out_size) {
    const float* x_graph = (const float*)d_in[0];
    const int*   edge    = (const int*)d_in[1];
    const int*   batch   = (const int*)d_in[2];
    const float* x_tab   = (const float*)d_in[3];
    const float* Wg1 = (const float*)d_in[4];  const float* bg1 = (const float*)d_in[5];
    const float* Wg2 = (const float*)d_in[6];  const float* bg2 = (const float*)d_in[7];
    const float* Wg3 = (const float*)d_in[8];  const float* bg3 = (const float*)d_in[9];
    const float* Wg4 = (const float*)d_in[10]; const float* bg4 = (const float*)d_in[11];
    const float* Wt1 = (const float*)d_in[12]; const float* bt1 = (const float*)d_in[13];
    const float* Wt2 = (const float*)d_in[14]; const float* bt2 = (const float*)d_in[15];
    const float* Wf1 = (const float*)d_in[16]; const float* bf1 = (const float*)d_in[17];
    const float* Wf2 = (const float*)d_in[18]; const float* bf2 = (const float*)d_in[19];
    const float* Wf3 = (const float*)d_in[20]; const float* bf3 = (const float*)d_in[21];

    int n = in_sizes[0] / 64;
    int E = in_sizes[1] / 2;
    int B = in_sizes[3] / 200;
    const int* src = edge;
    const int* dst = edge + E;

    float *Hp, *Xp, *catp, *t1p, *f1p, *f2p;
    unsigned char *whp, *wlp;
    cudaGetSymbolAddress((void**)&Hp,  g_H);
    cudaGetSymbolAddress((void**)&Xp,  g_X);
    cudaGetSymbolAddress((void**)&catp, g_cat);
    cudaGetSymbolAddress((void**)&t1p, g_t1);
    cudaGetSymbolAddress((void**)&f1p, g_f1);
    cudaGetSymbolAddress((void**)&f2p, g_f2);
    cudaGetSymbolAddress((void**)&whp, g_Wh);
    cudaGetSymbolAddress((void**)&wlp, g_Wl);

    cudaFuncSetAttribute(k_gemm_mma, cudaFuncAttributeMaxDynamicSharedMemorySize, 144 * 1024);

    int nb = (n + 1023) / 1024;

    k_init<<<256, 256>>>(n, B);
    k_count<<<(E + 255) / 256, 256>>>(dst, E);
    k_graph_ranges<<<(n + 255) / 256, 256>>>(batch, n);
    k_dinv<<<(n + 255) / 256, 256>>>(n);
    k_scan1<<<nb, 1024>>>(n);
    k_scan2<<<1, 32>>>(nb);
    k_scan3<<<nb, 1024>>>(n, E);
    k_scatter<<<(E + 255) / 256, 256>>>(src, dst, E);

    // W^T hi/lo bf16 images
    k_prep_w<<<(128 * 64 + 255) / 256, 256>>>(Wg1, 64, 0);
    k_prep_w<<<(128 * 128 + 255) / 256, 256>>>(Wg2, 128, 1);
    k_prep_w<<<(128 * 128 + 255) / 256, 256>>>(Wg3, 128, 2);
    k_prep_w<<<(128 * 128 + 255) / 256, 256>>>(Wg4, 128, 3);

    int gemm_blocks = (n + 127) / 128;
    int agg_blocks  = (n * 32 + 255) / 256;
    size_t smem64  = 4 * (size_t)128 * (64 + 8) * 2;    // 73,728
    size_t smem128 = 4 * (size_t)128 * (128 + 8) * 2;   // 139,264

    k_gemm_mma<<<gemm_blocks, 256, smem64 >>>(x_graph, whp,             wlp,             Hp, n, 64);
    k_aggregate<<<agg_blocks, 256>>>(bg1, n);
    k_gemm_mma<<<gemm_blocks, 256, smem128>>>(Xp,      whp + 1 * 32768, wlp + 1 * 32768, Hp, n, 128);
    k_aggregate<<<agg_blocks, 256>>>(bg2, n);
    k_gemm_mma<<<gemm_blocks, 256, smem128>>>(Xp,      whp + 2 * 32768, wlp + 2 * 32768, Hp, n, 128);
    k_aggregate<<<agg_blocks, 256>>>(bg3, n);
    k_gemm_mma<<<gemm_blocks, 256, smem128>>>(Xp,      whp + 3 * 32768, wlp + 3 * 32768, Hp, n, 128);
    k_aggregate<<<agg_blocks, 256>>>(bg4, n);

    k_pool<<<B, 128>>>(n);

    k_dense<<<B, 256>>>(x_tab, 200, Wt1, bt1, t1p, 256, 200, 256, 1);
    k_dense<<<B, 256>>>(t1p, 256, Wt2, bt2, catp + 256, 384, 256, 128, 1);
    k_dense<<<B, 256>>>(catp, 384, Wf1, bf1, f1p, 256, 384, 256, 1);
    k_dense<<<B, 256>>>(f1p, 256, Wf2, bf2, f2p, 128, 256, 128, 1);
    k_dense<<<B, 32>>>(f2p, 128, Wf3, bf3, (float*)d_out, 1, 128, 1, 2);
}

// round 7
// speedup vs baseline: 1.3994x; 1.1702x over previous
#include <cuda_runtime.h>
#include <cuda_bf16.h>
#include <cuda_fp16.h>
#include <math.h>
#include <stdint.h>

#define NN 100000
#define NE 1600000
#define NB 1024
#define HID 128

// ---------------- device scratch ---------------------------------------------
__device__ int   g_cnt[NN];
__device__ float g_dinv[NN];
__device__ int   g_rowptr[NN + 1];
__device__ int   g_cursor[NN];
__device__ int   g_bsums[256];
__device__ int   g_csr_src[NE];
__device__ float g_csr_norm[NE];
__device__ float g_Y[(size_t)NN * HID];                 // fp32 aggregation output
__device__ __half g_X16[(size_t)NN * HID];              // fp16 activations
__device__ int   g_gstart[NB];
__device__ int   g_gcnt[NB];
__device__ float g_cat[NB * 384];
__device__ float g_t1[NB * 256];
__device__ float g_f1[NB * 256];
__device__ float g_f2[NB * 128];
// bf16 hi/lo images of W^T per layer: row-major [128 n][K k]
__device__ __align__(16) unsigned char g_Wh[4][32768];
__device__ __align__(16) unsigned char g_Wl[4][32768];

// ---------------- ptx helpers -------------------------------------------------
__device__ __forceinline__ uint32_t smem_u32(const void* p) {
    uint32_t a;
    asm("{ .reg .u64 t; cvta.to.shared.u64 t, %1; cvt.u32.u64 %0, t; }" : "=r"(a) : "l"(p));
    return a;
}
__device__ __forceinline__ void ldm4(uint32_t* r, uint32_t addr) {
    asm volatile("ldmatrix.sync.aligned.m8n8.x4.shared.b16 {%0,%1,%2,%3}, [%4];"
                 : "=r"(r[0]), "=r"(r[1]), "=r"(r[2]), "=r"(r[3]) : "r"(addr));
}
__device__ __forceinline__ void mma_bf16(float* c, const uint32_t* a, uint32_t b0, uint32_t b1) {
    asm volatile("mma.sync.aligned.m16n8k16.row.col.f32.bf16.bf16.f32 "
                 "{%0,%1,%2,%3}, {%4,%5,%6,%7}, {%8,%9}, {%0,%1,%2,%3};"
                 : "+f"(c[0]), "+f"(c[1]), "+f"(c[2]), "+f"(c[3])
                 : "r"(a[0]), "r"(a[1]), "r"(a[2]), "r"(a[3]), "r"(b0), "r"(b1));
}

// ---------------- setup kernels ----------------------------------------------
__global__ void k_init(int n, int b) {
    int i = blockIdx.x * blockDim.x + threadIdx.x;
    int stride = gridDim.x * blockDim.x;
    for (int j = i; j < n; j += stride) g_cnt[j] = 0;
    for (int j = i; j < b; j += stride) { g_gstart[j] = 0x7fffffff; g_gcnt[j] = 0; }
}
__global__ void k_count(const int* __restrict__ dst, int E) {
    int e = blockIdx.x * blockDim.x + threadIdx.x;
    if (e < E) atomicAdd(&g_cnt[dst[e]], 1);
}
__global__ void k_graph_ranges(const int* __restrict__ batch, int n) {
    int i = blockIdx.x * blockDim.x + threadIdx.x;
    if (i < n) {
        int g = batch[i];
        atomicAdd(&g_gcnt[g], 1);
        atomicMin(&g_gstart[g], i);
    }
}
__global__ void k_dinv(int n) {
    int i = blockIdx.x * blockDim.x + threadIdx.x;
    if (i < n) g_dinv[i] = rsqrtf((float)(g_cnt[i] + 2));
}
__global__ void k_scan1(int n) {
    __shared__ int s[1024];
    int i = blockIdx.x * 1024 + threadIdx.x;
    int v = (i < n) ? g_cnt[i] : 0;
    s[threadIdx.x] = v;
    __syncthreads();
    for (int off = 1; off < 1024; off <<= 1) {
        int t = (threadIdx.x >= off) ? s[threadIdx.x - off] : 0;
        __syncthreads();
        s[threadIdx.x] += t;
        __syncthreads();
    }
    if (i < n) g_rowptr[i] = s[threadIdx.x] - v;
    if (threadIdx.x == 1023) g_bsums[blockIdx.x] = s[1023];
}
__global__ void k_scan2(int nb) {
    if (threadIdx.x == 0 && blockIdx.x == 0) {
        int acc = 0;
        for (int i = 0; i < nb; i++) { int v = g_bsums[i]; g_bsums[i] = acc; acc += v; }
    }
}
__global__ void k_scan3(int n, int E) {
    int i = blockIdx.x * 1024 + threadIdx.x;
    if (i < n) {
        int v = g_rowptr[i] + g_bsums[blockIdx.x];
        g_rowptr[i] = v;
        g_cursor[i] = v;
    }
    if (i == 0) g_rowptr[n] = E;
}
__global__ void k_scatter(const int* __restrict__ src, const int* __restrict__ dst, int E) {
    int e = blockIdx.x * blockDim.x + threadIdx.x;
    if (e < E) {
        int s = src[e], d = dst[e];
        int p = atomicAdd(&g_cursor[d], 1);
        g_csr_src[p] = s;
        g_csr_norm[p] = g_dinv[s] * g_dinv[d];
    }
}

// W [K x 128] fp32 -> W^T hi/lo bf16, row-major [n=128][K]
__global__ void k_prep_w(const float* __restrict__ W, int K, int layer) {
    int idx = blockIdx.x * blockDim.x + threadIdx.x;
    if (idx >= 128 * K) return;
    int nrow = idx / K, kcol = idx % K;
    float w = W[(size_t)kcol * 128 + nrow];
    __nv_bfloat16 hi = __float2bfloat16(w);
    __nv_bfloat16 lo = __float2bfloat16(w - __bfloat162float(hi));
    ((__nv_bfloat16*)g_Wh[layer])[idx] = hi;
    ((__nv_bfloat16*)g_Wl[layer])[idx] = lo;
}

// x_graph fp32 [n x 64] -> fp16 image in g_X16 (layout [n][64])
__global__ void k_tohalf64(const float* __restrict__ x, int n) {
    int i = blockIdx.x * blockDim.x + threadIdx.x;    // over n*32 float2s
    if (i < n * 32) {
        float2 v = *(const float2*)(x + (size_t)i * 2);
        ((half2*)g_X16)[i] = __floats2half2_rn(v.x, v.y);
    }
}

// ---------------- aggregation: Y = Agg(X16), atomic-free, warp per node ------
// width = 128: lane handles 4 halves
__global__ void k_agg128(int n) {
    int node = (blockIdx.x * blockDim.x + threadIdx.x) >> 5;
    int lane = threadIdx.x & 31;
    if (node >= n) return;
    float di = g_dinv[node];
    float sw = 2.f * di * di;
    const __half* X = g_X16;
    uint2 sv = *(const uint2*)(X + (size_t)node * 128 + lane * 4);
    float2 s0 = __half22float2(*(half2*)&sv.x);
    float2 s1 = __half22float2(*(half2*)&sv.y);
    float4 acc = make_float4(s0.x * sw, s0.y * sw, s1.x * sw, s1.y * sw);
    int beg = g_rowptr[node], end = g_rowptr[node + 1];
    for (int e = beg; e < end; e++) {
        int s = g_csr_src[e];
        float w = g_csr_norm[e];
        uint2 hv = *(const uint2*)(X + (size_t)s * 128 + lane * 4);
        float2 f0 = __half22float2(*(half2*)&hv.x);
        float2 f1 = __half22float2(*(half2*)&hv.y);
        acc.x += w * f0.x; acc.y += w * f0.y;
        acc.z += w * f1.x; acc.w += w * f1.y;
    }
    *(float4*)(g_Y + (size_t)node * 128 + lane * 4) = acc;
}
// width = 64 (layer 1): lane handles 2 halves
__global__ void k_agg64(int n) {
    int node = (blockIdx.x * blockDim.x + threadIdx.x) >> 5;
    int lane = threadIdx.x & 31;
    if (node >= n) return;
    float di = g_dinv[node];
    float sw = 2.f * di * di;
    const __half* X = g_X16;
    uint32_t sv = *(const uint32_t*)(X + (size_t)node * 64 + lane * 2);
    float2 s0 = __half22float2(*(half2*)&sv);
    float2 acc = make_float2(s0.x * sw, s0.y * sw);
    int beg = g_rowptr[node], end = g_rowptr[node + 1];
    for (int e = beg; e < end; e++) {
        int s = g_csr_src[e];
        float w = g_csr_norm[e];
        uint32_t hv = *(const uint32_t*)(X + (size_t)s * 64 + lane * 2);
        float2 f0 = __half22float2(*(half2*)&hv);
        acc.x += w * f0.x; acc.y += w * f0.y;
    }
    *(float2*)(g_Y + (size_t)node * 64 + lane * 2) = acc;
}

// ---------------- mma.sync GEMM: X16[M x 128] = relu(Y[M x K] @ W + b) -------
// hi/lo split: D = Ah*Wh + Al*Wh + Ah*Wl, fp32 accumulators; fp16 output.
// Block 128x128, 8 warps (4m x 2n), warp tile 32x64.
__global__ __launch_bounds__(256) void k_gemm_mma(const float* __restrict__ A,
                                                  const unsigned char* __restrict__ Wh,
                                                  const unsigned char* __restrict__ Wl,
                                                  const float* __restrict__ bias,
                                                  __half* __restrict__ Xout,
                                                  int M, int K) {
    extern __shared__ __align__(16) char smem[];
    const int SK = K + 8;
    const size_t tile = (size_t)128 * SK;
    __nv_bfloat16* sAh = (__nv_bfloat16*)smem;
    __nv_bfloat16* sAl = sAh + tile;
    __nv_bfloat16* sWh = sAl + tile;
    __nv_bfloat16* sWl = sWh + tile;

    const int tid = threadIdx.x;
    const int wid = tid >> 5, lane = tid & 31;
    const int wm = wid >> 1, wn = wid & 1;
    const int block_m = blockIdx.x * 128;

    {
        int k8 = K >> 3;
        for (int j = tid; j < 128 * k8; j += 256) {
            int r = j / k8, c = (j - r * k8) << 3;
            *(uint4*)(sWh + r * SK + c) = *(const uint4*)(Wh + ((size_t)r * K + c) * 2);
            *(uint4*)(sWl + r * SK + c) = *(const uint4*)(Wl + ((size_t)r * K + c) * 2);
        }
    }
    {
        int K4 = K >> 2;
        for (int j = tid; j < 32 * K; j += 256) {
            int r = j / K4, c = (j - r * K4) << 2;
            int gr = block_m + r; if (gr >= M) gr = M - 1;
            float4 v = *(const float4*)(A + (size_t)gr * K + c);
            __nv_bfloat162 h01 = __floats2bfloat162_rn(v.x, v.y);
            __nv_bfloat162 h23 = __floats2bfloat162_rn(v.z, v.w);
            float l0 = v.x - __low2float(h01), l1 = v.y - __high2float(h01);
            float l2 = v.z - __low2float(h23), l3 = v.w - __high2float(h23);
            __nv_bfloat162 lo01 = __floats2bfloat162_rn(l0, l1);
            __nv_bfloat162 lo23 = __floats2bfloat162_rn(l2, l3);
            *(uint2*)(sAh + r * SK + c) = make_uint2(*(uint32_t*)&h01, *(uint32_t*)&h23);
            *(uint2*)(sAl + r * SK + c) = make_uint2(*(uint32_t*)&lo01, *(uint32_t*)&lo23);
        }
    }
    __syncthreads();

    float acc[2][8][4];
#pragma unroll
    for (int i = 0; i < 2; i++)
#pragma unroll
        for (int j = 0; j < 8; j++)
#pragma unroll
            for (int q = 0; q < 4; q++) acc[i][j][q] = 0.f;

    const uint32_t uAh = smem_u32(sAh), uAl = smem_u32(sAl);
    const uint32_t uWh = smem_u32(sWh), uWl = smem_u32(sWl);
    const uint32_t a_row  = (uint32_t)(wm * 32 + (lane & 15));
    const uint32_t a_koff = (uint32_t)((lane >> 4) << 3);
    const uint32_t b_row  = (uint32_t)(wn * 64 + (((lane >> 4) & 1) << 3) + (lane & 7));
    const uint32_t b_koff = (uint32_t)(((lane >> 3) & 1) << 3);

    const int nks = K >> 4;
    for (int ks = 0; ks < nks; ks++) {
        const uint32_t kb = (uint32_t)(ks << 4);
        uint32_t ah0[4], ah1[4], al0[4], al1[4];
        ldm4(ah0, uAh + ((a_row) * SK + kb + a_koff) * 2);
        ldm4(ah1, uAh + ((a_row + 16) * SK + kb + a_koff) * 2);
        ldm4(al0, uAl + ((a_row) * SK + kb + a_koff) * 2);
        ldm4(al1, uAl + ((a_row + 16) * SK + kb + a_koff) * 2);
#pragma unroll
        for (int np = 0; np < 4; np++) {
            uint32_t wh[4], wl[4];
            uint32_t boff = ((b_row + (uint32_t)(np << 4)) * SK + kb + b_koff) * 2;
            ldm4(wh, uWh + boff);
            ldm4(wl, uWl + boff);
            int n0 = np * 2, n1 = np * 2 + 1;
            mma_bf16(acc[0][n0], ah0, wh[0], wh[1]);
            mma_bf16(acc[0][n1], ah0, wh[2], wh[3]);
            mma_bf16(acc[1][n0], ah1, wh[0], wh[1]);
            mma_bf16(acc[1][n1], ah1, wh[2], wh[3]);
            mma_bf16(acc[0][n0], al0, wh[0], wh[1]);
            mma_bf16(acc[0][n1], al0, wh[2], wh[3]);
            mma_bf16(acc[1][n0], al1, wh[0], wh[1]);
            mma_bf16(acc[1][n1], al1, wh[2], wh[3]);
            mma_bf16(acc[0][n0], ah0, wl[0], wl[1]);
            mma_bf16(acc[0][n1], ah0, wl[2], wl[3]);
            mma_bf16(acc[1][n0], ah1, wl[0], wl[1]);
            mma_bf16(acc[1][n1], ah1, wl[2], wl[3]);
        }
    }

    // epilogue: +bias, relu, fp16 store
    const int r_base = block_m + wm * 32 + (lane >> 2);
    const int c_base = wn * 64 + ((lane & 3) << 1);
#pragma unroll
    for (int mt = 0; mt < 2; mt++) {
        int r0 = r_base + mt * 16;
#pragma unroll
        for (int nt = 0; nt < 8; nt++) {
            int cc = c_base + nt * 8;
            float b0 = bias[cc], b1 = bias[cc + 1];
            if (r0 < M) {
                float v0 = fmaxf(acc[mt][nt][0] + b0, 0.f);
                float v1 = fmaxf(acc[mt][nt][1] + b1, 0.f);
                *(half2*)(Xout + (size_t)r0 * 128 + cc) = __floats2half2_rn(v0, v1);
            }
            if (r0 + 8 < M) {
                float v2 = fmaxf(acc[mt][nt][2] + b0, 0.f);
                float v3 = fmaxf(acc[mt][nt][3] + b1, 0.f);
                *(half2*)(Xout + (size_t)(r0 + 8) * 128 + cc) = __floats2half2_rn(v2, v3);
            }
        }
    }
}

// ---------------- pooling (fp16 input) ----------------------------------------
__global__ void k_pool(int n) {
    int g = blockIdx.x;
    int d = threadIdx.x;
    int beg = g_gstart[g], cnt = g_gcnt[g];
    float s = 0.f, mx = -3.402823e38f;
    for (int i = 0; i < cnt; i++) {
        float v = __half2float(g_X16[(size_t)(beg + i) * 128 + d]);
        s += v;
        mx = fmaxf(mx, v);
    }
    float mean = (cnt > 0) ? s / (float)cnt : 0.f;
    if (cnt == 0) mx = 0.f;
    g_cat[(size_t)g * 384 + d]       = mean;
    g_cat[(size_t)g * 384 + 128 + d] = mx;
}

// ---------------- small dense layers ------------------------------------------
__global__ void k_dense(const float* __restrict__ A, int lda,
                        const float* __restrict__ W, const float* __restrict__ b,
                        float* __restrict__ C, int ldc, int K, int N, int act) {
    __shared__ float sA[384];
    int m = blockIdx.x;
    for (int k = threadIdx.x; k < K; k += blockDim.x) sA[k] = A[(size_t)m * lda + k];
    __syncthreads();
    for (int nidx = threadIdx.x; nidx < N; nidx += blockDim.x) {
        float acc = b[nidx];
        for (int k = 0; k < K; k++) acc += sA[k] * W[(size_t)k * N + nidx];
        if (act == 1) acc = fmaxf(acc, 0.f);
        else if (act == 2) acc = 1.f / (1.f + expf(-acc));
        C[(size_t)m * ldc + nidx] = acc;
    }
}

// ---------------- launch ------------------------------------------------------
extern "C" void kernel_launch(void* const* d_in, const int* in_sizes, int n_in,
                              void* d_out, int out_size) {
    const float* x_graph = (const float*)d_in[0];
    const int*   edge    = (const int*)d_in[1];
    const int*   batch   = (const int*)d_in[2];
    const float* x_tab   = (const float*)d_in[3];
    const float* Wg1 = (const float*)d_in[4];  const float* bg1 = (const float*)d_in[5];
    const float* Wg2 = (const float*)d_in[6];  const float* bg2 = (const float*)d_in[7];
    const float* Wg3 = (const float*)d_in[8];  const float* bg3 = (const float*)d_in[9];
    const float* Wg4 = (const float*)d_in[10]; const float* bg4 = (const float*)d_in[11];
    const float* Wt1 = (const float*)d_in[12]; const float* bt1 = (const float*)d_in[13];
    const float* Wt2 = (const float*)d_in[14]; const float* bt2 = (const float*)d_in[15];
    const float* Wf1 = (const float*)d_in[16]; const float* bf1 = (const float*)d_in[17];
    const float* Wf2 = (const float*)d_in[18]; const float* bf2 = (const float*)d_in[19];
    const float* Wf3 = (const float*)d_in[20]; const float* bf3 = (const float*)d_in[21];

    int n = in_sizes[0] / 64;
    int E = in_sizes[1] / 2;
    int B = in_sizes[3] / 200;
    const int* src = edge;
    const int* dst = edge + E;

    float *Yp, *catp, *t1p, *f1p, *f2p;
    __half* x16p;
    unsigned char *whp, *wlp;
    cudaGetSymbolAddress((void**)&Yp,   g_Y);
    cudaGetSymbolAddress((void**)&x16p, g_X16);
    cudaGetSymbolAddress((void**)&catp, g_cat);
    cudaGetSymbolAddress((void**)&t1p, g_t1);
    cudaGetSymbolAddress((void**)&f1p, g_f1);
    cudaGetSymbolAddress((void**)&f2p, g_f2);
    cudaGetSymbolAddress((void**)&whp, g_Wh);
    cudaGetSymbolAddress((void**)&wlp, g_Wl);

    cudaFuncSetAttribute(k_gemm_mma, cudaFuncAttributeMaxDynamicSharedMemorySize, 144 * 1024);

    int nb = (n + 1023) / 1024;

    k_init<<<256, 256>>>(n, B);
    k_count<<<(E + 255) / 256, 256>>>(dst, E);
    k_graph_ranges<<<(n + 255) / 256, 256>>>(batch, n);
    k_dinv<<<(n + 255) / 256, 256>>>(n);
    k_scan1<<<nb, 1024>>>(n);
    k_scan2<<<1, 32>>>(nb);
    k_scan3<<<nb, 1024>>>(n, E);
    k_scatter<<<(E + 255) / 256, 256>>>(src, dst, E);

    // weight images + fp16 input image
    k_prep_w<<<(128 * 64 + 255) / 256, 256>>>(Wg1, 64, 0);
    k_prep_w<<<(128 * 128 + 255) / 256, 256>>>(Wg2, 128, 1);
    k_prep_w<<<(128 * 128 + 255) / 256, 256>>>(Wg3, 128, 2);
    k_prep_w<<<(128 * 128 + 255) / 256, 256>>>(Wg4, 128, 3);
    k_tohalf64<<<(n * 32 + 255) / 256, 256>>>(x_graph, n);

    int gemm_blocks = (n + 127) / 128;
    int agg_blocks  = (n * 32 + 255) / 256;
    size_t smem64  = 4 * (size_t)128 * (64 + 8) * 2;
    size_t smem128 = 4 * (size_t)128 * (128 + 8) * 2;

    // layer 1: aggregate 64-wide input, then GEMM(K=64) with fused bias+relu
    k_agg64<<<agg_blocks, 256>>>(n);
    k_gemm_mma<<<gemm_blocks, 256, smem64 >>>(Yp, whp,             wlp,             bg1, x16p, n, 64);
    // layers 2-4: aggregate 128-wide fp16, GEMM(K=128)
    k_agg128<<<agg_blocks, 256>>>(n);
    k_gemm_mma<<<gemm_blocks, 256, smem128>>>(Yp, whp + 1 * 32768, wlp + 1 * 32768, bg2, x16p, n, 128);
    k_agg128<<<agg_blocks, 256>>>(n);
    k_gemm_mma<<<gemm_blocks, 256, smem128>>>(Yp, whp + 2 * 32768, wlp + 2 * 32768, bg3, x16p, n, 128);
    k_agg128<<<agg_blocks, 256>>>(n);
    k_gemm_mma<<<gemm_blocks, 256, smem128>>>(Yp, whp + 3 * 32768, wlp + 3 * 32768, bg4, x16p, n, 128);

    k_pool<<<B, 128>>>(n);

    k_dense<<<B, 256>>>(x_tab, 200, Wt1, bt1, t1p, 256, 200, 256, 1);
    k_dense<<<B, 256>>>(t1p, 256, Wt2, bt2, catp + 256, 384, 256, 128, 1);
    k_dense<<<B, 256>>>(catp, 384, Wf1, bf1, f1p, 256, 384, 256, 1);
    k_dense<<<B, 256>>>(f1p, 256, Wf2, bf2, f2p, 128, 256, 128, 1);
    k_dense<<<B, 32>>>(f2p, 128, Wf3, bf3, (float*)d_out, 1, 128, 1, 2);
}